// round 4
// baseline (speedup 1.0000x reference)
#include <cuda_runtime.h>

// LocalSpatialEncoding: enc = [rel(3), |rel|] -> (W1,BN,ReLU)[4] -> (W2,BN,ReLU)[8]
// B=8, N=16384, K=16. Output (B,N,K,8) fp32.
// R4: BN-folded weights in __constant__ (LDCU -> uniform regs, zero RF cost),
//     4 consecutive points/thread with float4 neighbor loads.

#define LSE_EPS 1e-5f
#define TOTAL (8 * 16384 * 16)       // 2097152 points
#define THREADS 256
#define PTS 4

// Folded weight layout: [0:16) W1', [16:20) t1, [20:52) W2', [52:60) t2
__constant__ float c_w[60];
__device__ float g_staging[60];

__global__ void lse_prep(const float* __restrict__ W1, const float* __restrict__ g1,
                         const float* __restrict__ b1, const float* __restrict__ m1,
                         const float* __restrict__ v1,
                         const float* __restrict__ W2, const float* __restrict__ g2,
                         const float* __restrict__ b2, const float* __restrict__ m2,
                         const float* __restrict__ v2)
{
    int t = threadIdx.x;
    if (t < 16) {
        int o = t >> 2;
        float s = g1[o] * rsqrtf(v1[o] + LSE_EPS);
        g_staging[t] = W1[t] * s;
        if ((t & 3) == 0) g_staging[16 + o] = b1[o] - m1[o] * s;
    } else if (t < 48) {
        int i = t - 16;
        int o = i >> 2;
        float s = g2[o] * rsqrtf(v2[o] + LSE_EPS);
        g_staging[20 + i] = W2[i] * s;
        if ((i & 3) == 0) g_staging[52 + o] = b2[o] - m2[o] * s;
    }
}

__global__ void __launch_bounds__(THREADS, 5)
lse_main(const float* __restrict__ coords,
         const float* __restrict__ nbr,
         float* __restrict__ out)
{
    int q  = blockIdx.x * THREADS + threadIdx.x;   // thread index: 4 pts each
    int p0 = q * PTS;                              // p0 % 16 in {0,4,8,12} -> same center

    // Neighbor coords of 4 points: 12 floats = 3 x float4, contiguous & coalesced.
    const float4* nb4 = reinterpret_cast<const float4*>(nbr) + (size_t)q * 3;
    float4 va = __ldg(nb4 + 0);
    float4 vb = __ldg(nb4 + 1);
    float4 vc = __ldg(nb4 + 2);

    // Center coord: shared by 4 consecutive threads -> L1 broadcast.
    const float* cp = coords + (size_t)(p0 >> 4) * 3;
    float c0 = __ldg(cp + 0);
    float c1 = __ldg(cp + 1);
    float c2 = __ldg(cp + 2);

    float px[PTS], py[PTS], pz[PTS];
    px[0] = va.x; py[0] = va.y; pz[0] = va.z;
    px[1] = va.w; py[1] = vb.x; pz[1] = vb.y;
    px[2] = vb.z; py[2] = vb.w; pz[2] = vc.x;
    px[3] = vc.y; py[3] = vc.z; pz[3] = vc.w;

    float4* o4 = reinterpret_cast<float4*>(out) + (size_t)q * (PTS * 2);

#pragma unroll
    for (int i = 0; i < PTS; i++) {
        float r0 = px[i] - c0;
        float r1 = py[i] - c1;
        float r2 = pz[i] - c2;
        float dist = sqrtf(fmaf(r0, r0, fmaf(r1, r1, r2 * r2)));

        float h[4];
#pragma unroll
        for (int o = 0; o < 4; o++) {
            float acc = c_w[16 + o];
            acc = fmaf(r0,   c_w[o * 4 + 0], acc);
            acc = fmaf(r1,   c_w[o * 4 + 1], acc);
            acc = fmaf(r2,   c_w[o * 4 + 2], acc);
            acc = fmaf(dist, c_w[o * 4 + 3], acc);
            h[o] = fmaxf(acc, 0.0f);
        }

        float y[8];
#pragma unroll
        for (int o = 0; o < 8; o++) {
            float acc = c_w[52 + o];
            acc = fmaf(h[0], c_w[20 + o * 4 + 0], acc);
            acc = fmaf(h[1], c_w[20 + o * 4 + 1], acc);
            acc = fmaf(h[2], c_w[20 + o * 4 + 2], acc);
            acc = fmaf(h[3], c_w[20 + o * 4 + 3], acc);
            y[o] = fmaxf(acc, 0.0f);
        }

        o4[2 * i + 0] = make_float4(y[0], y[1], y[2], y[3]);
        o4[2 * i + 1] = make_float4(y[4], y[5], y[6], y[7]);
    }
}

extern "C" void kernel_launch(void* const* d_in, const int* in_sizes, int n_in,
                              void* d_out, int out_size)
{
    const float* coords = (const float*)d_in[0];
    const float* nbr    = (const float*)d_in[1];
    const float* W1     = (const float*)d_in[2];
    const float* g1     = (const float*)d_in[3];
    const float* b1     = (const float*)d_in[4];
    const float* m1     = (const float*)d_in[5];
    const float* v1     = (const float*)d_in[6];
    const float* W2     = (const float*)d_in[7];
    const float* g2     = (const float*)d_in[8];
    const float* b2     = (const float*)d_in[9];
    const float* m2     = (const float*)d_in[10];
    const float* v2     = (const float*)d_in[11];
    float* out = (float*)d_out;

    // 1) Fold BN into weights (device side).
    lse_prep<<<1, 64>>>(W1, g1, b1, m1, v1, W2, g2, b2, m2, v2);

    // 2) Move folded weights into the constant bank (D2D async, capturable).
    void* staging_addr = nullptr;
    cudaGetSymbolAddress(&staging_addr, g_staging);
    cudaMemcpyToSymbolAsync(c_w, staging_addr, 60 * sizeof(float), 0,
                            cudaMemcpyDeviceToDevice, 0);

    // 3) Main kernel.
    int blocks = TOTAL / (THREADS * PTS);   // 2048
    lse_main<<<blocks, THREADS>>>(coords, nbr, out);
}

// round 5
// speedup vs baseline: 1.3013x; 1.3013x over previous
#include <cuda_runtime.h>

// LocalSpatialEncoding: enc = [rel(3), |rel|] -> (W1,BN,ReLU)[4] -> (W2,BN,ReLU)[8]
// B=8, N=16384, K=16. Output (B,N,K,8) fp32.
// R5: constant-bank folded weights + per-warp smem transpose so all STG.128
//     are lane-contiguous (4 lines/instr, minimal L2 store requests).

#define LSE_EPS 1e-5f
#define TOTAL (8 * 16384 * 16)       // 2097152 points
#define THREADS 256
#define WARPS (THREADS / 32)
#define ROWSTRIDE 36                 // 32 cols + 4 pad  (== 4 mod 32 -> conflict-free)

// Folded weight layout: [0:16) W1', [16:20) t1, [20:52) W2', [52:60) t2
__constant__ float c_w[60];
__device__ float g_staging[60];

__global__ void lse_prep(const float* __restrict__ W1, const float* __restrict__ g1,
                         const float* __restrict__ b1, const float* __restrict__ m1,
                         const float* __restrict__ v1,
                         const float* __restrict__ W2, const float* __restrict__ g2,
                         const float* __restrict__ b2, const float* __restrict__ m2,
                         const float* __restrict__ v2)
{
    int t = threadIdx.x;
    if (t < 16) {
        int o = t >> 2;
        float s = g1[o] * rsqrtf(v1[o] + LSE_EPS);
        g_staging[t] = W1[t] * s;
        if ((t & 3) == 0) g_staging[16 + o] = b1[o] - m1[o] * s;
    } else if (t < 48) {
        int i = t - 16;
        int o = i >> 2;
        float s = g2[o] * rsqrtf(v2[o] + LSE_EPS);
        g_staging[20 + i] = W2[i] * s;
        if ((i & 3) == 0) g_staging[52 + o] = b2[o] - m2[o] * s;
    }
}

__global__ void __launch_bounds__(THREADS)
lse_main(const float* __restrict__ coords,
         const float* __restrict__ nbr,
         float* __restrict__ out)
{
    // Per-warp transpose buffer: [warp][channel row][lane], padded rows.
    __shared__ float sbuf[WARPS][8][ROWSTRIDE];

    int tid  = threadIdx.x;
    int warp = tid >> 5;
    int lane = tid & 31;
    int p    = blockIdx.x * THREADS + tid;        // one point per thread

    // ---- Load: neighbor (contiguous 12B/thread) + center (broadcast) ----
    const float* nb = nbr + (size_t)p * 3;
    float n0 = __ldg(nb + 0);
    float n1 = __ldg(nb + 1);
    float n2 = __ldg(nb + 2);

    const float* cp = coords + (size_t)(p >> 4) * 3;
    float r0 = n0 - __ldg(cp + 0);
    float r1 = n1 - __ldg(cp + 1);
    float r2 = n2 - __ldg(cp + 2);
    float dist = sqrtf(fmaf(r0, r0, fmaf(r1, r1, r2 * r2)));

    // ---- Layer 1 (weights from constant bank -> uniform regs) ----
    float h[4];
#pragma unroll
    for (int o = 0; o < 4; o++) {
        float acc = c_w[16 + o];
        acc = fmaf(r0,   c_w[o * 4 + 0], acc);
        acc = fmaf(r1,   c_w[o * 4 + 1], acc);
        acc = fmaf(r2,   c_w[o * 4 + 2], acc);
        acc = fmaf(dist, c_w[o * 4 + 3], acc);
        h[o] = fmaxf(acc, 0.0f);
    }

    // ---- Layer 2, write channels to smem transposed ----
#pragma unroll
    for (int o = 0; o < 8; o++) {
        float acc = c_w[52 + o];
        acc = fmaf(h[0], c_w[20 + o * 4 + 0], acc);
        acc = fmaf(h[1], c_w[20 + o * 4 + 1], acc);
        acc = fmaf(h[2], c_w[20 + o * 4 + 2], acc);
        acc = fmaf(h[3], c_w[20 + o * 4 + 3], acc);
        sbuf[warp][o][lane] = fmaxf(acc, 0.0f);   // banks (4o+lane)%32: conflict-free
    }

    __syncwarp();

    // ---- Read back lane-contiguous float4s and store coalesced ----
    // Warp's output = 32 points * 8 floats = 64 float4. Lane handles f = lane, lane+32.
    // float4 f covers point f/2, channels (f%2)*4 .. +3.
    int warp_pt_base = blockIdx.x * THREADS + warp * 32;   // first point of this warp
    float4* o4 = reinterpret_cast<float4*>(out) + (size_t)warp_pt_base * 2;

#pragma unroll
    for (int k = 0; k < 2; k++) {
        int f    = lane + 32 * k;
        int row0 = (f & 1) * 4;
        int col  = f >> 1;
        float4 v;
        v.x = sbuf[warp][row0 + 0][col];
        v.y = sbuf[warp][row0 + 1][col];
        v.z = sbuf[warp][row0 + 2][col];
        v.w = sbuf[warp][row0 + 3][col];
        o4[f] = v;   // lanes write contiguous 512B per instruction
    }
}

extern "C" void kernel_launch(void* const* d_in, const int* in_sizes, int n_in,
                              void* d_out, int out_size)
{
    const float* coords = (const float*)d_in[0];
    const float* nbr    = (const float*)d_in[1];
    const float* W1     = (const float*)d_in[2];
    const float* g1     = (const float*)d_in[3];
    const float* b1     = (const float*)d_in[4];
    const float* m1     = (const float*)d_in[5];
    const float* v1     = (const float*)d_in[6];
    const float* W2     = (const float*)d_in[7];
    const float* g2     = (const float*)d_in[8];
    const float* b2     = (const float*)d_in[9];
    const float* m2     = (const float*)d_in[10];
    const float* v2     = (const float*)d_in[11];
    float* out = (float*)d_out;

    // 1) Fold BN into weights (device side).
    lse_prep<<<1, 64>>>(W1, g1, b1, m1, v1, W2, g2, b2, m2, v2);

    // 2) Move folded weights into the constant bank (D2D async, capturable).
    void* staging_addr = nullptr;
    cudaGetSymbolAddress(&staging_addr, g_staging);
    cudaMemcpyToSymbolAsync(c_w, staging_addr, 60 * sizeof(float), 0,
                            cudaMemcpyDeviceToDevice, 0);

    // 3) Main kernel.
    int blocks = TOTAL / THREADS;   // 8192
    lse_main<<<blocks, THREADS>>>(coords, nbr, out);
}

// round 7
// speedup vs baseline: 1.4024x; 1.0777x over previous
#include <cuda_runtime.h>

// LocalSpatialEncoding: enc=[rel(3),|rel|] -> (W1,BN,ReLU)[4] -> (W2,BN,ReLU)[8]
// B=8,N=16384,K=16. Output (B,N,K,8) fp32.
// R7 (= R6 resubmit after infra failure). ONE kernel. Per-block BN fold into
// smem (duplicated float2 pairs), 4 points/thread as two f32x2 packed pairs
// (FFMA2), weight LDS.64 amortized over 4 points, conflict-free STS.128
// transpose + coalesced STG.128.

#define LSE_EPS 1e-5f
#define TOTAL   (8 * 16384 * 16)     // 2097152 points
#define THREADS 256
#define WARPS   8
#define PTW     128                  // points per warp (32 lanes * 4)
#define STRIDE  132                  // 128 + 4 pad words (conflict-free, 16B-mult rows)

typedef unsigned long long u64;

__device__ __forceinline__ u64 pk2(float lo, float hi) {
    u64 r; asm("mov.b64 %0,{%1,%2};" : "=l"(r) : "f"(lo), "f"(hi)); return r;
}
__device__ __forceinline__ void upk2(u64 v, float& lo, float& hi) {
    asm("mov.b64 {%0,%1},%2;" : "=f"(lo), "=f"(hi) : "l"(v));
}
__device__ __forceinline__ u64 fma2(u64 a, u64 b, u64 c) {
    u64 d; asm("fma.rn.f32x2 %0,%1,%2,%3;" : "=l"(d) : "l"(a), "l"(b), "l"(c)); return d;
}
__device__ __forceinline__ u64 add2(u64 a, u64 b) {
    u64 d; asm("add.rn.f32x2 %0,%1,%2;" : "=l"(d) : "l"(a), "l"(b)); return d;
}
__device__ __forceinline__ u64 mul2(u64 a, u64 b) {
    u64 d; asm("mul.rn.f32x2 %0,%1,%2;" : "=l"(d) : "l"(a), "l"(b)); return d;
}
__device__ __forceinline__ float sqrt_ap(float x) {
    float r; asm("sqrt.approx.f32 %0,%1;" : "=f"(r) : "f"(x)); return r;
}
__device__ __forceinline__ u64 relu2(u64 v) {
    float a, b; upk2(v, a, b);
    return pk2(fmaxf(a, 0.0f), fmaxf(b, 0.0f));
}

__global__ void __launch_bounds__(THREADS)
lse_main(const float* __restrict__ coords,
         const float* __restrict__ nbr,
         const float* __restrict__ W1, const float* __restrict__ g1,
         const float* __restrict__ b1, const float* __restrict__ m1,
         const float* __restrict__ v1,
         const float* __restrict__ W2, const float* __restrict__ g2,
         const float* __restrict__ b2, const float* __restrict__ m2,
         const float* __restrict__ v2,
         float* __restrict__ out)
{
    // BN-folded weights as duplicated (w,w) pairs for f32x2 operands.
    // Layout (float2 idx): [0:16) W1', [16:20) t1, [20:52) W2', [52:60) t2
    __shared__ __align__(16) float2 swb[60];
    __shared__ __align__(16) float  sbuf[WARPS][8][STRIDE];

    int t = threadIdx.x;
    if (t < 16) {
        int o = t >> 2;
        float s = g1[o] * rsqrtf(v1[o] + LSE_EPS);
        float w = W1[t] * s;
        swb[t] = make_float2(w, w);
        if ((t & 3) == 0) { float bb = b1[o] - m1[o] * s; swb[16 + o] = make_float2(bb, bb); }
    } else if (t < 48) {
        int i = t - 16;
        int o = i >> 2;
        float s = g2[o] * rsqrtf(v2[o] + LSE_EPS);
        float w = W2[i] * s;
        swb[20 + i] = make_float2(w, w);
        if ((i & 3) == 0) { float bb = b2[o] - m2[o] * s; swb[52 + o] = make_float2(bb, bb); }
    }
    __syncthreads();
    const u64* wp = reinterpret_cast<const u64*>(swb);   // LDS.64 broadcast reads

    int g    = blockIdx.x * THREADS + t;   // thread id: owns points 4g..4g+3
    int warp = t >> 5;
    int lane = t & 31;

    // ---- Loads: 12 neighbor floats = 3 x LDG.128 (48B contiguous, coalesced) ----
    const float4* nb4 = reinterpret_cast<const float4*>(nbr) + (size_t)g * 3;
    float4 va = __ldg(nb4 + 0);
    float4 vb = __ldg(nb4 + 1);
    float4 vc = __ldg(nb4 + 2);

    // Center: 4 pts/thread share one center (4 | 16); 4 consecutive threads broadcast.
    const float* cp = coords + (size_t)(g >> 2) * 3;
    float c0 = __ldg(cp + 0), c1 = __ldg(cp + 1), c2 = __ldg(cp + 2);
    u64 nc0 = pk2(-c0, -c0), nc1 = pk2(-c1, -c1), nc2 = pk2(-c2, -c2);

    // Pack pairs: pair0 = (pt0, pt1), pair1 = (pt2, pt3)
    u64 x0 = add2(pk2(va.x, va.w), nc0);
    u64 y0 = add2(pk2(va.y, vb.x), nc1);
    u64 z0 = add2(pk2(va.z, vb.y), nc2);
    u64 x1 = add2(pk2(vb.z, vc.y), nc0);
    u64 y1 = add2(pk2(vb.w, vc.z), nc1);
    u64 z1 = add2(pk2(vc.x, vc.w), nc2);

    u64 d20 = fma2(x0, x0, fma2(y0, y0, mul2(z0, z0)));
    u64 d21 = fma2(x1, x1, fma2(y1, y1, mul2(z1, z1)));
    float da, db;
    upk2(d20, da, db);  u64 dd0 = pk2(sqrt_ap(da), sqrt_ap(db));
    upk2(d21, da, db);  u64 dd1 = pk2(sqrt_ap(da), sqrt_ap(db));

    // ---- Layer 1: each weight LDS.64 serves both pairs (4 points) ----
    u64 h0[4], h1[4];
#pragma unroll
    for (int o = 0; o < 4; o++) {
        u64 w0 = wp[o * 4 + 0], w1_ = wp[o * 4 + 1];
        u64 w2_ = wp[o * 4 + 2], w3 = wp[o * 4 + 3], bb = wp[16 + o];
        h0[o] = relu2(fma2(x0, w0, fma2(y0, w1_, fma2(z0, w2_, fma2(dd0, w3, bb)))));
        h1[o] = relu2(fma2(x1, w0, fma2(y1, w1_, fma2(z1, w2_, fma2(dd1, w3, bb)))));
    }

    // ---- Layer 2 + transposed smem store (STS.128, conflict-free) ----
#pragma unroll
    for (int o = 0; o < 8; o++) {
        u64 w0 = wp[20 + o * 4 + 0], w1_ = wp[20 + o * 4 + 1];
        u64 w2_ = wp[20 + o * 4 + 2], w3 = wp[20 + o * 4 + 3], bb = wp[52 + o];
        u64 a = relu2(fma2(h0[0], w0, fma2(h0[1], w1_, fma2(h0[2], w2_, fma2(h0[3], w3, bb)))));
        u64 b = relu2(fma2(h1[0], w0, fma2(h1[1], w1_, fma2(h1[2], w2_, fma2(h1[3], w3, bb)))));
        float4 v;
        upk2(a, v.x, v.y);   // channel o of pts 4*lane, 4*lane+1
        upk2(b, v.z, v.w);   // channel o of pts 4*lane+2, 4*lane+3
        *reinterpret_cast<float4*>(&sbuf[warp][o][4 * lane]) = v;
    }
    __syncwarp();

    // ---- Read back lane-contiguous float4s, store coalesced (STG.128) ----
    // Warp region: 128 pts * 8 ch = 256 float4. Lane handles f = lane + 32k.
    int warpbase = blockIdx.x * (THREADS * 4) + warp * PTW;
    float4* o4 = reinterpret_cast<float4*>(out) + (size_t)warpbase * 2;
#pragma unroll
    for (int k = 0; k < 8; k++) {
        int f  = lane + 32 * k;
        int pt = f >> 1;
        int cb = (f & 1) * 4;
        float4 v;
        v.x = sbuf[warp][cb + 0][pt];
        v.y = sbuf[warp][cb + 1][pt];
        v.z = sbuf[warp][cb + 2][pt];
        v.w = sbuf[warp][cb + 3][pt];
        o4[f] = v;   // 32 lanes -> 512B contiguous per instruction
    }
}

extern "C" void kernel_launch(void* const* d_in, const int* in_sizes, int n_in,
                              void* d_out, int out_size)
{
    const float* coords = (const float*)d_in[0];
    const float* nbr    = (const float*)d_in[1];
    const float* W1     = (const float*)d_in[2];
    const float* g1     = (const float*)d_in[3];
    const float* b1     = (const float*)d_in[4];
    const float* m1     = (const float*)d_in[5];
    const float* v1     = (const float*)d_in[6];
    const float* W2     = (const float*)d_in[7];
    const float* g2     = (const float*)d_in[8];
    const float* b2     = (const float*)d_in[9];
    const float* m2     = (const float*)d_in[10];
    const float* v2     = (const float*)d_in[11];
    float* out = (float*)d_out;

    int blocks = TOTAL / (THREADS * 4);   // 2048
    lse_main<<<blocks, THREADS>>>(coords, nbr, W1, g1, b1, m1, v1,
                                  W2, g2, b2, m2, v2, out);
}

// round 8
// speedup vs baseline: 1.5541x; 1.1081x over previous
#include <cuda_runtime.h>

// LocalSpatialEncoding: enc=[rel(3),|rel|] -> (W1,BN,ReLU)[4] -> (W2,BN,ReLU)[8]
// B=8,N=16384,K=16. Output (B,N,K,8) fp32.
// R8: single kernel; per-block BN fold into smem; 2 consecutive pts/thread
// (32768 warps); weights fetched as 15 broadcast LDS.128; transpose store
// with stride-68 rows (STS.64 2-phase, readback conflict-free) + STG.128.

#define LSE_EPS 1e-5f
#define TOTAL   (8 * 16384 * 16)   // 2097152 points
#define THREADS 256
#define WARPS   8
#define PTW     64                 // points per warp (32 lanes * 2)
#define STR     68                 // row stride in words: 4*68 % 32 == 16 -> no conflicts

__device__ __forceinline__ float sqrt_ap(float x) {
    float r; asm("sqrt.approx.f32 %0,%1;" : "=f"(r) : "f"(x)); return r;
}

__global__ void __launch_bounds__(THREADS)
lse_main(const float* __restrict__ coords,
         const float* __restrict__ nbr,
         const float* __restrict__ W1, const float* __restrict__ g1,
         const float* __restrict__ b1, const float* __restrict__ m1,
         const float* __restrict__ v1,
         const float* __restrict__ W2, const float* __restrict__ g2,
         const float* __restrict__ b2, const float* __restrict__ m2,
         const float* __restrict__ v2,
         float* __restrict__ out)
{
    // Folded weights, float4-addressable:
    //   w4[0..3]  = W1' rows     w4[4]     = t1
    //   w4[5..12] = W2' rows     w4[13,14] = t2
    __shared__ __align__(16) float sw[60];
    __shared__ __align__(16) float sbuf[WARPS][8][STR];

    int t = threadIdx.x;
    if (t < 16) {
        int o = t >> 2;
        float s = g1[o] * rsqrtf(v1[o] + LSE_EPS);
        sw[t] = W1[t] * s;
        if ((t & 3) == 0) sw[16 + o] = b1[o] - m1[o] * s;
    } else if (t < 48) {
        int i = t - 16;
        int o = i >> 2;
        float s = g2[o] * rsqrtf(v2[o] + LSE_EPS);
        sw[20 + i] = W2[i] * s;
        if ((i & 3) == 0) sw[52 + o] = b2[o] - m2[o] * s;
    }
    __syncthreads();
    const float4* w4 = reinterpret_cast<const float4*>(sw);

    int g    = blockIdx.x * THREADS + t;   // thread owns points 2g, 2g+1
    int warp = t >> 5;
    int lane = t & 31;

    // ---- Loads: 6 neighbor floats = 3 x LDG.64 contiguous; center broadcast (8 thr) ----
    const float2* nb2 = reinterpret_cast<const float2*>(nbr) + (size_t)g * 3;
    float2 va = __ldg(nb2 + 0);
    float2 vb = __ldg(nb2 + 1);
    float2 vc = __ldg(nb2 + 2);

    const float* cp = coords + (size_t)(g >> 3) * 3;
    float c0 = __ldg(cp + 0), c1 = __ldg(cp + 1), c2 = __ldg(cp + 2);

    // pt0 = (va.x, va.y, vb.x), pt1 = (vb.y, vc.x, vc.y)
    float ax = va.x - c0, ay = va.y - c1, az = vb.x - c2;
    float bx = vb.y - c0, by = vc.x - c1, bz = vc.y - c2;
    float da = sqrt_ap(fmaf(ax, ax, fmaf(ay, ay, az * az)));
    float db = sqrt_ap(fmaf(bx, bx, fmaf(by, by, bz * bz)));

    // ---- Layer 1: one LDS.128 per output row, serves both points ----
    float4 t1v = w4[4];
    const float* t1p = reinterpret_cast<const float*>(&t1v);
    float ha[4], hb[4];
#pragma unroll
    for (int o = 0; o < 4; o++) {
        float4 w = w4[o];
        float acc = t1p[o];
        ha[o] = fmaxf(fmaf(ax, w.x, fmaf(ay, w.y, fmaf(az, w.z, fmaf(da, w.w, acc)))), 0.0f);
        hb[o] = fmaxf(fmaf(bx, w.x, fmaf(by, w.y, fmaf(bz, w.z, fmaf(db, w.w, acc)))), 0.0f);
    }

    // ---- Layer 2: one LDS.128 per output row; channel result -> transposed smem ----
    float4 t2a = w4[13], t2b = w4[14];
    const float* t2p0 = reinterpret_cast<const float*>(&t2a);
    const float* t2p1 = reinterpret_cast<const float*>(&t2b);
#pragma unroll
    for (int o = 0; o < 8; o++) {
        float4 w = w4[5 + o];
        float bias = (o < 4) ? t2p0[o] : t2p1[o - 4];
        float ya = fmaxf(fmaf(ha[0], w.x, fmaf(ha[1], w.y, fmaf(ha[2], w.z, fmaf(ha[3], w.w, bias)))), 0.0f);
        float yb = fmaxf(fmaf(hb[0], w.x, fmaf(hb[1], w.y, fmaf(hb[2], w.z, fmaf(hb[3], w.w, bias)))), 0.0f);
        // STS.64: banks (4o + 2*lane) % 32, each bank written twice = 2 phases (min)
        *reinterpret_cast<float2*>(&sbuf[warp][o][2 * lane]) = make_float2(ya, yb);
    }
    __syncwarp();

    // ---- Readback + coalesced STG.128 ----
    // Warp region: 64 pts * 8 ch = 128 float4. Lane handles f = lane + 32k, k<4.
    // f -> point pt=f>>1, channels cb=(f&1)*4 .. +3.
    int warpbase = blockIdx.x * (THREADS * 2) + warp * PTW;
    float4* o4 = reinterpret_cast<float4*>(out) + (size_t)warpbase * 2;
#pragma unroll
    for (int k = 0; k < 4; k++) {
        int f  = lane + 32 * k;
        int pt = f >> 1;
        int cb = (f & 1) * 4;
        float4 v;
        v.x = sbuf[warp][cb + 0][pt];
        v.y = sbuf[warp][cb + 1][pt];
        v.z = sbuf[warp][cb + 2][pt];
        v.w = sbuf[warp][cb + 3][pt];
        o4[f] = v;   // 32 lanes -> 512B contiguous per STG.128
    }
}

extern "C" void kernel_launch(void* const* d_in, const int* in_sizes, int n_in,
                              void* d_out, int out_size)
{
    const float* coords = (const float*)d_in[0];
    const float* nbr    = (const float*)d_in[1];
    const float* W1     = (const float*)d_in[2];
    const float* g1     = (const float*)d_in[3];
    const float* b1     = (const float*)d_in[4];
    const float* m1     = (const float*)d_in[5];
    const float* v1     = (const float*)d_in[6];
    const float* W2     = (const float*)d_in[7];
    const float* g2     = (const float*)d_in[8];
    const float* b2     = (const float*)d_in[9];
    const float* m2     = (const float*)d_in[10];
    const float* v2     = (const float*)d_in[11];
    float* out = (float*)d_out;

    int blocks = TOTAL / (THREADS * 2);   // 4096
    lse_main<<<blocks, THREADS>>>(coords, nbr, W1, g1, b1, m1, v1,
                                  W2, g2, b2, m2, v2, out);
}